// round 9
// baseline (speedup 1.0000x reference)
#include <cuda_runtime.h>
#include <cstdint>
#include <cstdio>

// ----------------------------------------------------------------------------
// Real spherical harmonic transform -> REAL PART of output (R8 finding:
// d_out is out_size x 4 bytes; complex64 reference reduced to float32 = real).
//   Re X[row,m] = sum_j E[row,j] * (s*cos(2pi m j/720)),  row = b*360+k
//   out[b,n,m]  = sum_k Re X[b,k,m] * W[m,n,k]            (float32)
// ----------------------------------------------------------------------------

#define NTH   360
#define NLAM  720
#define NM    361
#define NB    8
#define ROWS  (NB*NTH) // 2880
#define KP    368
#define MP    384

#define X_ELEMS (NB*NTH*NLAM)       // 2,073,600
#define W_ELEMS (NM*NTH*NTH)        // 46,785,600
#define OUT_ELEMS (NB*NTH*NM)       // 1,039,680 float32

__device__ float g_C  [KP * MP];     // [j][m] = s*cos(2pi m j / 720)
__device__ float g_E  [ROWS * KP];   // [row][j] even fold
__device__ float g_Xre[MP * ROWS];   // [m][row]

// ---------------------------------------------------------------- build table
__global__ void k_build_B() {
    int l = blockIdx.x;          // 0..367
    int m = threadIdx.x;         // 0..383
    float vc = 0.f;
    if (l <= 360) {
        int p = (l * m) % 720;
        float c = cospif((float)p * (1.0f / 360.0f));
        vc = 0.008726646259971648f * c;      // 2*pi/720
    }
    g_C[l * MP + m] = vc;
}

// ---------------------------------------------------------------- fold E
__global__ void k_fold(const float* __restrict__ x) {
    int idx = blockIdx.x * blockDim.x + threadIdx.x;
    if (idx >= ROWS * KP) return;
    int r = idx / KP;
    int j = idx - r * KP;
    float e = 0.f;
    if (j <= 360) {
        const float* xr = x + r * NLAM;
        if (j == 0)        e = xr[0];
        else if (j == 360) e = xr[360];
        else               e = xr[j] + xr[NLAM - j];
    }
    g_E[idx] = e;
}

// ---------------------------------------------------------------- GEMM1 (DFT)
// Xre[row,m] = sum_j E[row,j] * C[j,m]
#define G_AP 65
__global__ void __launch_bounds__(128) k_gemm1() {
    __shared__ float sE[16 * G_AP];   // [kk][row]
    __shared__ float sC[16 * 64];     // [kk][m]

    const int tid = threadIdx.x;
    const int ty  = tid >> 4;         // 0..7
    const int tx  = tid & 15;         // 0..15
    const int m0   = blockIdx.x * 64;
    const int row0 = blockIdx.y * 64;

    float acc[8][4];
#pragma unroll
    for (int i = 0; i < 8; ++i)
#pragma unroll
        for (int j = 0; j < 4; ++j) acc[i][j] = 0.f;

    for (int k0 = 0; k0 < KP; k0 += 16) {
#pragma unroll
        for (int t = 0; t < 8; ++t) {
            int i  = tid + t * 128;
            int r  = i >> 4;
            int kk = i & 15;
            sE[kk * G_AP + r] = g_E[(row0 + r) * KP + (k0 + kk)];
        }
#pragma unroll
        for (int t = 0; t < 8; ++t) {
            int i  = tid + t * 128;
            int kk = i >> 6;
            int mm = i & 63;
            sC[kk * 64 + mm] = g_C[(k0 + kk) * MP + (m0 + mm)];
        }
        __syncthreads();
#pragma unroll
        for (int kk = 0; kk < 16; ++kk) {
            float e[8], c[4];
#pragma unroll
            for (int i = 0; i < 8; ++i) e[i] = sE[kk * G_AP + 8 * i + ty];
#pragma unroll
            for (int j = 0; j < 4; ++j) c[j] = sC[kk * 64 + 16 * j + tx];
#pragma unroll
            for (int i = 0; i < 8; ++i)
#pragma unroll
                for (int j = 0; j < 4; ++j)
                    acc[i][j] = fmaf(e[i], c[j], acc[i][j]);
        }
        __syncthreads();
    }
#pragma unroll
    for (int j = 0; j < 4; ++j) {
        int m = m0 + 16 * j + tx;
#pragma unroll
        for (int i = 0; i < 8; ++i) {
            int r = row0 + 8 * i + ty;
            g_Xre[m * ROWS + r] = acc[i][j];
        }
    }
}

// ---------------------------------------------------------------- contraction
// One block per m; thread t owns n in {2t, 2t+1}, all 8 batches.
// out[(b*360+n)*361 + m] = sum_k Xre[m][b*360+k] * W[m*360*360 + n*360 + k]
#define KC    12
#define WPAD  13
__global__ void __launch_bounds__(192) k_contract(const float* __restrict__ W,
                                                  float* __restrict__ out) {
    __shared__ float Xr[ROWS];          // 11520 B
    __shared__ float Ws[NTH * WPAD];    // 18720 B

    const int m   = blockIdx.x;
    const int tid = threadIdx.x;
    const int n0  = 2 * tid;
    const bool live = (n0 < NTH);

    for (int i = tid; i < ROWS; i += 192) Xr[i] = g_Xre[m * ROWS + i];

    const float* Wm = W + (size_t)m * (NTH * NTH);

    float ar[8][2];
#pragma unroll
    for (int b = 0; b < 8; ++b) { ar[b][0] = 0.f; ar[b][1] = 0.f; }

    for (int k0 = 0; k0 < NTH; k0 += KC) {
        __syncthreads();
        for (int i = tid; i < NTH * KC; i += 192) {
            int n  = i / KC;
            int kk = i - n * KC;
            Ws[n * WPAD + kk] = Wm[n * NTH + k0 + kk];
        }
        __syncthreads();
        if (live) {
#pragma unroll
            for (int kk = 0; kk < KC; ++kk) {
                int k = k0 + kk;
                float wa = Ws[n0 * WPAD + kk];
                float wb = Ws[(n0 + 1) * WPAD + kk];
#pragma unroll
                for (int b = 0; b < 8; ++b) {
                    float xr = Xr[b * NTH + k];
                    ar[b][0] = fmaf(xr, wa, ar[b][0]);
                    ar[b][1] = fmaf(xr, wb, ar[b][1]);
                }
            }
        }
    }
    if (live) {
#pragma unroll
        for (int b = 0; b < 8; ++b) {
            out[(size_t)(b * NTH + n0)     * NM + m] = ar[b][0];
            out[(size_t)(b * NTH + n0 + 1) * NM + m] = ar[b][1];
        }
    }
}

// ---------------------------------------------------------------- host diag
static bool sync_check(const char* stage) {
    cudaError_t e = cudaDeviceSynchronize();
    if (e == cudaSuccess) e = cudaGetLastError();
    fprintf(stderr, "[diag] stage %-10s : %s\n", stage,
            e == cudaSuccess ? "OK" : cudaGetErrorString(e));
    fflush(stderr);
    return e == cudaSuccess;
}

// ---------------------------------------------------------------- launch
extern "C" void kernel_launch(void* const* d_in, const int* in_sizes, int n_in,
                              void* d_out, int out_size) {
    const float* x = nullptr;
    const float* w = nullptr;
    for (int i = 0; i < n_in; ++i) {
        if (in_sizes[i] == X_ELEMS && !x) x = (const float*)d_in[i];
        else if (in_sizes[i] == W_ELEMS && !w) w = (const float*)d_in[i];
    }
    float* out = (float*)d_out;
    if (!x || !w) return;

    cudaStreamCaptureStatus st = cudaStreamCaptureStatusNone;
    cudaStreamIsCapturing((cudaStream_t)0, &st);
    const bool capturing = (st != cudaStreamCaptureStatusNone);

    if (!capturing) {
        // staged run with per-stage error reporting (correctness phase only)
        k_build_B<<<KP, MP>>>();
        if (!sync_check("build_B")) return;
        k_fold<<<(ROWS * KP + 255) / 256, 256>>>(x);
        if (!sync_check("fold")) return;
        k_gemm1<<<dim3(MP / 64, ROWS / 64), 128>>>();
        if (!sync_check("gemm1")) return;
        k_contract<<<NM, 192>>>(w, out);
        if (!sync_check("contract")) return;
        return;
    }

    // capture path: plain launches only
    k_build_B<<<KP, MP>>>();
    k_fold<<<(ROWS * KP + 255) / 256, 256>>>(x);
    k_gemm1<<<dim3(MP / 64, ROWS / 64), 128>>>();
    k_contract<<<NM, 192>>>(w, out);
}

// round 10
// speedup vs baseline: 1.5025x; 1.5025x over previous
#include <cuda_runtime.h>
#include <cstdint>
#include <cstdio>

// ----------------------------------------------------------------------------
// Real spherical harmonic transform -> real part (float32 out).
//   Re X[row,m] = sum_j E[row,j] * (s*cos(2pi m j/720)),  row = b*360+k
//   out[b,n,m]  = sum_k Re X[b,k,m] * W[m,n,k]
// R9: contract rewritten: n-split x2, double-buffered W stream (reg prefetch),
// float4 global loads, conflict-free smem layout.
// ----------------------------------------------------------------------------

#define NTH   360
#define NLAM  720
#define NM    361
#define NB    8
#define ROWS  (NB*NTH) // 2880
#define KP    368
#define MP    384

#define X_ELEMS (NB*NTH*NLAM)       // 2,073,600
#define W_ELEMS (NM*NTH*NTH)        // 46,785,600
#define OUT_ELEMS (NB*NTH*NM)       // 1,039,680 float32

__device__ float g_C  [KP * MP];     // [j][m] = s*cos(2pi m j / 720)
__device__ float g_E  [ROWS * KP];   // [row][j] even fold
__device__ float g_Xre[MP * ROWS];   // [m][row]

// ---------------------------------------------------------------- build table
__global__ void k_build_B() {
    int l = blockIdx.x;          // 0..367
    int m = threadIdx.x;         // 0..383
    float vc = 0.f;
    if (l <= 360) {
        int p = (l * m) % 720;
        float c = cospif((float)p * (1.0f / 360.0f));
        vc = 0.008726646259971648f * c;      // 2*pi/720
    }
    g_C[l * MP + m] = vc;
}

// ---------------------------------------------------------------- fold E
__global__ void k_fold(const float* __restrict__ x) {
    int idx = blockIdx.x * blockDim.x + threadIdx.x;
    if (idx >= ROWS * KP) return;
    int r = idx / KP;
    int j = idx - r * KP;
    float e = 0.f;
    if (j <= 360) {
        const float* xr = x + r * NLAM;
        if (j == 0)        e = xr[0];
        else if (j == 360) e = xr[360];
        else               e = xr[j] + xr[NLAM - j];
    }
    g_E[idx] = e;
}

// ---------------------------------------------------------------- GEMM1 (DFT)
// Xre[row,m] = sum_j E[row,j] * C[j,m]
#define G_AP 65
__global__ void __launch_bounds__(128) k_gemm1() {
    __shared__ float sE[16 * G_AP];   // [kk][row]
    __shared__ float sC[16 * 64];     // [kk][m]

    const int tid = threadIdx.x;
    const int ty  = tid >> 4;         // 0..7
    const int tx  = tid & 15;         // 0..15
    const int m0   = blockIdx.x * 64;
    const int row0 = blockIdx.y * 64;

    float acc[8][4];
#pragma unroll
    for (int i = 0; i < 8; ++i)
#pragma unroll
        for (int j = 0; j < 4; ++j) acc[i][j] = 0.f;

    for (int k0 = 0; k0 < KP; k0 += 16) {
#pragma unroll
        for (int t = 0; t < 8; ++t) {
            int i  = tid + t * 128;
            int r  = i >> 4;
            int kk = i & 15;
            sE[kk * G_AP + r] = g_E[(row0 + r) * KP + (k0 + kk)];
        }
#pragma unroll
        for (int t = 0; t < 8; ++t) {
            int i  = tid + t * 128;
            int kk = i >> 6;
            int mm = i & 63;
            sC[kk * 64 + mm] = g_C[(k0 + kk) * MP + (m0 + mm)];
        }
        __syncthreads();
#pragma unroll
        for (int kk = 0; kk < 16; ++kk) {
            float e[8], c[4];
#pragma unroll
            for (int i = 0; i < 8; ++i) e[i] = sE[kk * G_AP + 8 * i + ty];
#pragma unroll
            for (int j = 0; j < 4; ++j) c[j] = sC[kk * 64 + 16 * j + tx];
#pragma unroll
            for (int i = 0; i < 8; ++i)
#pragma unroll
                for (int j = 0; j < 4; ++j)
                    acc[i][j] = fmaf(e[i], c[j], acc[i][j]);
        }
        __syncthreads();
    }
#pragma unroll
    for (int j = 0; j < 4; ++j) {
        int m = m0 + 16 * j + tx;
#pragma unroll
        for (int i = 0; i < 8; ++i) {
            int r = row0 + 8 * i + ty;
            g_Xre[m * ROWS + r] = acc[i][j];
        }
    }
}

// ---------------------------------------------------------------- contraction
// Grid (361, 2): block = (m, n-half). 192 threads; thread t owns n = t (<180),
// all 8 batches. Double-buffered W staging: prefetch next chunk into registers
// (float4) during compute, STS to alternate smem buffer.
#define NSPL 2
#define NPB  (NTH / NSPL)          // 180 n per block
#define KC2  16
#define WST  17                    // Ws row stride (conflict-free)
#define NPH  ((NTH + KC2 - 1) / KC2)   // 23 phases (last ragged, zero-padded)

__global__ void __launch_bounds__(192) k_contract(const float* __restrict__ W,
                                                  float* __restrict__ out) {
    __shared__ float Xs[ROWS + KC2];          // + pad for ragged last phase
    __shared__ float Ws[2][NPB * WST];        // double buffer, 2 x 12.2 KB

    const int m   = blockIdx.x;
    const int ys  = blockIdx.y;
    const int tid = threadIdx.x;
    const int n   = tid;                      // local n, live if < NPB
    const bool live = (n < NPB);

    const float* Wm = W + (size_t)m * (NTH * NTH) + (size_t)ys * NPB * NTH;

    // stage X column (+ zeroed pad)
    for (int i = tid; i < ROWS + KC2; i += 192)
        Xs[i] = (i < ROWS) ? g_Xre[m * ROWS + i] : 0.f;

    float4 pf[4];

    // prefetch phase k0 into registers (float4; zero beyond k=360)
    auto prefetch = [&](int k0) {
#pragma unroll
        for (int u = 0; u < 4; ++u) {
            int i = tid + 192 * u;            // float4 index in [0, 720)
            float4 v = make_float4(0.f, 0.f, 0.f, 0.f);
            if (i < NPB * (KC2 / 4)) {
                int nl = i >> 2;              // local n row
                int k  = k0 + (i & 3) * 4;
                if (k < NTH)
                    v = *reinterpret_cast<const float4*>(Wm + (size_t)nl * NTH + k);
            }
            pf[u] = v;
        }
    };
    auto store_buf = [&](int buf) {
#pragma unroll
        for (int u = 0; u < 4; ++u) {
            int i = tid + 192 * u;
            if (i < NPB * (KC2 / 4)) {
                int nl = i >> 2;
                int kb = (i & 3) * 4;
                float* dst = &Ws[buf][nl * WST + kb];
                dst[0] = pf[u].x; dst[1] = pf[u].y;
                dst[2] = pf[u].z; dst[3] = pf[u].w;
            }
        }
    };

    prefetch(0);
    store_buf(0);
    __syncthreads();

    float acc[8];
#pragma unroll
    for (int b = 0; b < 8; ++b) acc[b] = 0.f;

    for (int p = 0; p < NPH; ++p) {
        const int k0 = p * KC2;
        if (p + 1 < NPH) prefetch(k0 + KC2);   // LDGs in flight during compute
        const int buf = p & 1;
        if (live) {
#pragma unroll
            for (int kk = 0; kk < KC2; ++kk) {
                float wv = Ws[buf][n * WST + kk];   // conflict-free
                int k = k0 + kk;                     // wv==0 when k>=360
#pragma unroll
                for (int b = 0; b < 8; ++b)
                    acc[b] = fmaf(Xs[b * NTH + k], wv, acc[b]);  // broadcast
            }
        }
        __syncthreads();
        if (p + 1 < NPH) {
            store_buf((p + 1) & 1);
            __syncthreads();
        }
    }

    if (live) {
        const int ng = ys * NPB + n;
#pragma unroll
        for (int b = 0; b < 8; ++b)
            out[(size_t)(b * NTH + ng) * NM + m] = acc[b];
    }
}

// ---------------------------------------------------------------- host diag
static bool sync_check(const char* stage) {
    cudaError_t e = cudaDeviceSynchronize();
    if (e == cudaSuccess) e = cudaGetLastError();
    if (e != cudaSuccess) {
        fprintf(stderr, "[diag] stage %-10s : %s\n", stage, cudaGetErrorString(e));
        fflush(stderr);
        return false;
    }
    return true;
}

// ---------------------------------------------------------------- launch
extern "C" void kernel_launch(void* const* d_in, const int* in_sizes, int n_in,
                              void* d_out, int out_size) {
    const float* x = nullptr;
    const float* w = nullptr;
    for (int i = 0; i < n_in; ++i) {
        if (in_sizes[i] == X_ELEMS && !x) x = (const float*)d_in[i];
        else if (in_sizes[i] == W_ELEMS && !w) w = (const float*)d_in[i];
    }
    float* out = (float*)d_out;
    if (!x || !w) return;

    cudaStreamCaptureStatus st = cudaStreamCaptureStatusNone;
    cudaStreamIsCapturing((cudaStream_t)0, &st);
    const bool capturing = (st != cudaStreamCaptureStatusNone);

    if (!capturing) {
        k_build_B<<<KP, MP>>>();
        if (!sync_check("build_B")) return;
        k_fold<<<(ROWS * KP + 255) / 256, 256>>>(x);
        if (!sync_check("fold")) return;
        k_gemm1<<<dim3(MP / 64, ROWS / 64), 128>>>();
        if (!sync_check("gemm1")) return;
        k_contract<<<dim3(NM, NSPL), 192>>>(w, out);
        if (!sync_check("contract")) return;
        return;
    }

    k_build_B<<<KP, MP>>>();
    k_fold<<<(ROWS * KP + 255) / 256, 256>>>(x);
    k_gemm1<<<dim3(MP / 64, ROWS / 64), 128>>>();
    k_contract<<<dim3(NM, NSPL), 192>>>(w, out);
}

// round 11
// speedup vs baseline: 1.6637x; 1.1073x over previous
#include <cuda_runtime.h>
#include <cstdint>
#include <cstdio>

// ----------------------------------------------------------------------------
// Real spherical harmonic transform -> real part (float32 out).
//   Re X[row,m] = sum_j E[row,j] * (s*cos(2pi m j/720)),  row = b*360+k
//   out[b,n,m]  = sum_k Re X[b,k,m] * W[m,n,k]
// R11: contract inner loop vectorized (LDS.128 for W and X), gemm1 retiled
// (128x64x16, 256 thr, float4) with padded rows (no guards).
// ----------------------------------------------------------------------------

#define NTH   360
#define NLAM  720
#define NM    361
#define NB    8
#define ROWS  (NB*NTH) // 2880
#define ROWS_P 2944    // padded to multiple of 128
#define KP    368
#define MP    384

#define X_ELEMS (NB*NTH*NLAM)       // 2,073,600
#define W_ELEMS (NM*NTH*NTH)        // 46,785,600
#define OUT_ELEMS (NB*NTH*NM)       // 1,039,680 float32

__device__ float g_C  [KP * MP];        // [j][m] = s*cos(2pi m j / 720)
__device__ float g_E  [ROWS_P * KP];    // [row][j] even fold (pad rows zero)
__device__ float g_Xre[MP * ROWS_P];    // [m][row]

// ---------------------------------------------------------------- build table
__global__ void k_build_B() {
    int l = blockIdx.x;          // 0..367
    int m = threadIdx.x;         // 0..383
    float vc = 0.f;
    if (l <= 360) {
        int p = (l * m) % 720;
        float c = cospif((float)p * (1.0f / 360.0f));
        vc = 0.008726646259971648f * c;      // 2*pi/720
    }
    g_C[l * MP + m] = vc;
}

// ---------------------------------------------------------------- fold E
__global__ void k_fold(const float* __restrict__ x) {
    int idx = blockIdx.x * blockDim.x + threadIdx.x;
    if (idx >= ROWS_P * KP) return;
    int r = idx / KP;
    int j = idx - r * KP;
    float e = 0.f;
    if (r < ROWS && j <= 360) {
        const float* xr = x + r * NLAM;
        if (j == 0)        e = xr[0];
        else if (j == 360) e = xr[360];
        else               e = xr[j] + xr[NLAM - j];
    }
    g_E[idx] = e;
}

// ---------------------------------------------------------------- GEMM1 (DFT)
// Xre[row,m] = sum_j E[row,j] * C[j,m].  BM=128, BN=64, BK=16, 256 threads,
// per-thread 8 consecutive rows x 4 consecutive m.
#define EPAD 132   // sE row length (floats, mult of 4)
#define CPAD 68    // sC row length
__global__ void __launch_bounds__(256) k_gemm1() {
    __shared__ __align__(16) float sE[16 * EPAD];   // [kk][row(128)]
    __shared__ __align__(16) float sC[16 * CPAD];   // [kk][m(64)]

    const int tid = threadIdx.x;
    const int ty  = tid >> 4;         // 0..15 -> rows ty*8 .. ty*8+7
    const int tx  = tid & 15;         // 0..15 -> m tx*4 .. tx*4+3
    const int m0   = blockIdx.x * 64;
    const int row0 = blockIdx.y * 128;

    float acc[8][4];
#pragma unroll
    for (int i = 0; i < 8; ++i)
#pragma unroll
        for (int j = 0; j < 4; ++j) acc[i][j] = 0.f;

    for (int k0 = 0; k0 < KP; k0 += 16) {
        // sE: 128 rows x 16 kk = 512 float4 loads; 2 per thread, transposed STS
#pragma unroll
        for (int t = 0; t < 2; ++t) {
            int i = tid + t * 256;        // 0..511
            int r = i >> 2;               // 0..127
            int q = i & 3;                // float4 within row
            float4 v = *reinterpret_cast<const float4*>(
                &g_E[(row0 + r) * KP + k0 + 4 * q]);
            sE[(4 * q + 0) * EPAD + r] = v.x;
            sE[(4 * q + 1) * EPAD + r] = v.y;
            sE[(4 * q + 2) * EPAD + r] = v.z;
            sE[(4 * q + 3) * EPAD + r] = v.w;
        }
        // sC: 16 kk x 64 m = 256 float4; 1 per thread (vector STS)
        {
            int kk = tid >> 4;            // 0..15
            int q  = tid & 15;            // 0..15 -> m 4q
            float4 v = *reinterpret_cast<const float4*>(
                &g_C[(k0 + kk) * MP + m0 + 4 * q]);
            *reinterpret_cast<float4*>(&sC[kk * CPAD + 4 * q]) = v;
        }
        __syncthreads();
#pragma unroll
        for (int kk = 0; kk < 16; ++kk) {
            float4 e0 = *reinterpret_cast<const float4*>(&sE[kk * EPAD + ty * 8]);
            float4 e1 = *reinterpret_cast<const float4*>(&sE[kk * EPAD + ty * 8 + 4]);
            float4 c  = *reinterpret_cast<const float4*>(&sC[kk * CPAD + tx * 4]);
            float e[8] = {e0.x, e0.y, e0.z, e0.w, e1.x, e1.y, e1.z, e1.w};
            float cv[4] = {c.x, c.y, c.z, c.w};
#pragma unroll
            for (int i = 0; i < 8; ++i)
#pragma unroll
                for (int j = 0; j < 4; ++j)
                    acc[i][j] = fmaf(e[i], cv[j], acc[i][j]);
        }
        __syncthreads();
    }
    // store: per m, 8 consecutive rows -> 2 float4 STG
#pragma unroll
    for (int j = 0; j < 4; ++j) {
        int m = m0 + tx * 4 + j;
        float4 v0 = make_float4(acc[0][j], acc[1][j], acc[2][j], acc[3][j]);
        float4 v1 = make_float4(acc[4][j], acc[5][j], acc[6][j], acc[7][j]);
        *reinterpret_cast<float4*>(&g_Xre[m * ROWS_P + row0 + ty * 8])     = v0;
        *reinterpret_cast<float4*>(&g_Xre[m * ROWS_P + row0 + ty * 8 + 4]) = v1;
    }
}

// ---------------------------------------------------------------- contraction
// Grid (361, 2). 192 threads; thread t owns n=t (<180), all 8 batches.
// Double-buffered W stream (reg prefetch, float4), LDS.128 compute loop.
#define NSPL 2
#define NPB  (NTH / NSPL)          // 180
#define KC2  16
#define WST  20                    // Ws row stride (floats, 16B-aligned rows)
#define NPH  ((NTH + KC2 - 1) / KC2)   // 23

__global__ void __launch_bounds__(192) k_contract(const float* __restrict__ W,
                                                  float* __restrict__ out) {
    __shared__ __align__(16) float Xs[ROWS + KC2];
    __shared__ __align__(16) float Ws[2][NPB * WST];   // 2 x 14.4 KB

    const int m   = blockIdx.x;
    const int ys  = blockIdx.y;
    const int tid = threadIdx.x;
    const int n   = tid;
    const bool live = (n < NPB);

    const float* Wm = W + (size_t)m * (NTH * NTH) + (size_t)ys * NPB * NTH;

    for (int i = tid; i < ROWS + KC2; i += 192)
        Xs[i] = (i < ROWS) ? g_Xre[m * ROWS_P + i] : 0.f;

    float4 pf[4];
    auto prefetch = [&](int k0) {
#pragma unroll
        for (int u = 0; u < 4; ++u) {
            int i = tid + 192 * u;            // float4 slot, 720 used
            float4 v = make_float4(0.f, 0.f, 0.f, 0.f);
            if (i < NPB * (KC2 / 4)) {
                int nl = i >> 2;
                int k  = k0 + (i & 3) * 4;
                if (k < NTH)
                    v = *reinterpret_cast<const float4*>(Wm + (size_t)nl * NTH + k);
            }
            pf[u] = v;
        }
    };
    auto store_buf = [&](int buf) {
#pragma unroll
        for (int u = 0; u < 4; ++u) {
            int i = tid + 192 * u;
            if (i < NPB * (KC2 / 4)) {
                int nl = i >> 2;
                int kb = (i & 3) * 4;
                *reinterpret_cast<float4*>(&Ws[buf][nl * WST + kb]) = pf[u];
            }
        }
    };

    prefetch(0);
    store_buf(0);
    __syncthreads();

    float acc[8];
#pragma unroll
    for (int b = 0; b < 8; ++b) acc[b] = 0.f;

    for (int p = 0; p < NPH; ++p) {
        const int k0 = p * KC2;
        if (p + 1 < NPH) prefetch(k0 + KC2);      // LDGs overlap compute
        const int buf = p & 1;
        if (live) {
#pragma unroll
            for (int q = 0; q < KC2 / 4; ++q) {
                float4 wv = *reinterpret_cast<const float4*>(&Ws[buf][n * WST + 4 * q]);
#pragma unroll
                for (int b = 0; b < 8; ++b) {
                    float4 xv = *reinterpret_cast<const float4*>(
                        &Xs[b * NTH + k0 + 4 * q]);   // warp-broadcast
                    acc[b] = fmaf(xv.x, wv.x, acc[b]);
                    acc[b] = fmaf(xv.y, wv.y, acc[b]);
                    acc[b] = fmaf(xv.z, wv.z, acc[b]);
                    acc[b] = fmaf(xv.w, wv.w, acc[b]);
                }
            }
        }
        __syncthreads();
        if (p + 1 < NPH) {
            store_buf((p + 1) & 1);
            __syncthreads();
        }
    }

    if (live) {
        const int ng = ys * NPB + n;
#pragma unroll
        for (int b = 0; b < 8; ++b)
            out[(size_t)(b * NTH + ng) * NM + m] = acc[b];
    }
}

// ---------------------------------------------------------------- host diag
static bool sync_check(const char* stage) {
    cudaError_t e = cudaDeviceSynchronize();
    if (e == cudaSuccess) e = cudaGetLastError();
    if (e != cudaSuccess) {
        fprintf(stderr, "[diag] stage %-10s : %s\n", stage, cudaGetErrorString(e));
        fflush(stderr);
        return false;
    }
    return true;
}

// ---------------------------------------------------------------- launch
extern "C" void kernel_launch(void* const* d_in, const int* in_sizes, int n_in,
                              void* d_out, int out_size) {
    const float* x = nullptr;
    const float* w = nullptr;
    for (int i = 0; i < n_in; ++i) {
        if (in_sizes[i] == X_ELEMS && !x) x = (const float*)d_in[i];
        else if (in_sizes[i] == W_ELEMS && !w) w = (const float*)d_in[i];
    }
    float* out = (float*)d_out;
    if (!x || !w) return;

    cudaStreamCaptureStatus st = cudaStreamCaptureStatusNone;
    cudaStreamIsCapturing((cudaStream_t)0, &st);
    const bool capturing = (st != cudaStreamCaptureStatusNone);

    if (!capturing) {
        k_build_B<<<KP, MP>>>();
        if (!sync_check("build_B")) return;
        k_fold<<<(ROWS_P * KP + 255) / 256, 256>>>(x);
        if (!sync_check("fold")) return;
        k_gemm1<<<dim3(MP / 64, ROWS_P / 128), 256>>>();
        if (!sync_check("gemm1")) return;
        k_contract<<<dim3(NM, NSPL), 192>>>(w, out);
        if (!sync_check("contract")) return;
        return;
    }

    k_build_B<<<KP, MP>>>();
    k_fold<<<(ROWS_P * KP + 255) / 256, 256>>>(x);
    k_gemm1<<<dim3(MP / 64, ROWS_P / 128), 256>>>();
    k_contract<<<dim3(NM, NSPL), 192>>>(w, out);
}